// round 2
// baseline (speedup 1.0000x reference)
#include <cuda_runtime.h>
#include <stdint.h>

#define NN     4096
#define FIN    256
#define NHEADS 4
#define FOUT_  64
#define CTOT   256   // NHEADS*FOUT_
#define RB     8     // rows of i per attention block
#define TJ     32    // j-tile staged in shared

// Scratch (no allocations allowed): h = x@W, e1 = h.a1 (per head), e2 = h.a2
__device__ float g_h [NN * CTOT];
__device__ float g_e1[NN * NHEADS];
__device__ float g_e2[NN * NHEADS];

__device__ __forceinline__ float lrelu(float s) { return fmaxf(s, 0.2f * s); }

// ---------------------------------------------------------------------------
// Kernel 1: h = x @ W  (4096x256 @ 256x256), plus e1[n][h], e2[n][h].
// 8 node-rows per block so W (L2-resident) is read 8x less.
// ---------------------------------------------------------------------------
__global__ __launch_bounds__(256) void k_proj(const float* __restrict__ x,
                                              const float* __restrict__ W,
                                              const float* __restrict__ a)
{
    const int t  = threadIdx.x;         // output channel c = t
    const int n0 = blockIdx.x * 8;

    __shared__ float sx[8][FIN];
    {
        const float4* xs = (const float4*)(x + (size_t)n0 * FIN);
        float4* ss = (float4*)&sx[0][0];
        ss[t]       = xs[t];
        ss[t + 256] = xs[t + 256];
    }
    __syncthreads();

    float acc[8];
#pragma unroll
    for (int r = 0; r < 8; r++) acc[r] = 0.f;

#pragma unroll 4
    for (int k = 0; k < FIN; k++) {
        const float wv = W[k * CTOT + t];
#pragma unroll
        for (int r = 0; r < 8; r++) acc[r] += sx[r][k] * wv;
    }

    const int f = t & 63;
    const float a1 = a[f];
    const float a2 = a[64 + f];

    __shared__ float red1[8], red2[8];
#pragma unroll
    for (int r = 0; r < 8; r++) {
        g_h[(size_t)(n0 + r) * CTOT + t] = acc[r];
        float p1 = acc[r] * a1;
        float p2 = acc[r] * a2;
#pragma unroll
        for (int o = 16; o; o >>= 1) {
            p1 += __shfl_xor_sync(0xffffffffu, p1, o);
            p2 += __shfl_xor_sync(0xffffffffu, p2, o);
        }
        const int w = t >> 5;
        if ((t & 31) == 0) { red1[w] = p1; red2[w] = p2; }
        __syncthreads();
        if (t < 4) {
            g_e1[(size_t)(n0 + r) * NHEADS + t] = red1[2 * t] + red1[2 * t + 1];
            g_e2[(size_t)(n0 + r) * NHEADS + t] = red2[2 * t] + red2[2 * t + 1];
        }
        __syncthreads();
    }
}

// ---------------------------------------------------------------------------
// Kernel 2: masked softmax + aggregation, 8 rows i per block.
//   warp w owns row i0+w for: adjacency bitmask build, row max, exp-weights.
//   Stage B: thread t = (sp<<6)|(hh<<4)|f4 accumulates float4 of features
//   for all 8 rows over its jl-slice -> 32 FFMA per 9 LDS (FFMA-bound).
// ---------------------------------------------------------------------------
__global__ __launch_bounds__(256) void k_attn(const int* __restrict__ adj,
                                              float* __restrict__ out)
{
    const int t    = threadIdx.x;
    const int lane = t & 31;
    const int wrp  = t >> 5;            // 0..7 = local row
    const int i0   = blockIdx.x * RB;

    __shared__ unsigned amask[RB][NN / 32];   // 4 KB
    __shared__ float    hsh[TJ * CTOT];       // 32 KB (reused for epilogue)
    __shared__ float4   wsh[RB][TJ];          // 4 KB
    __shared__ float4   zsh[RB];

    // 1. adjacency -> bitmask (adj read exactly once per row)
    {
        const int* arow = adj + (size_t)(i0 + wrp) * NN;
#pragma unroll 4
        for (int b = 0; b < NN / 32; b++) {
            unsigned m = __ballot_sync(0xffffffffu, arow[b * 32 + lane] != 0);
            if (lane == 0) amask[wrp][b] = m;
        }
    }
    const float4 e1r = *(const float4*)(g_e1 + (size_t)(i0 + wrp) * NHEADS);
    __syncthreads();

    // 2. exact row max per head (warp wrp -> row wrp)
    float4 m4 = make_float4(-1e30f, -1e30f, -1e30f, -1e30f);
    for (int it = 0; it < NN / 32; it++) {
        const unsigned word = amask[wrp][it];
        if (word & (1u << lane)) {
            const float4 e2j = *(const float4*)(g_e2 + (size_t)(it * 32 + lane) * NHEADS);
            m4.x = fmaxf(m4.x, lrelu(e1r.x + e2j.x));
            m4.y = fmaxf(m4.y, lrelu(e1r.y + e2j.y));
            m4.z = fmaxf(m4.z, lrelu(e1r.z + e2j.z));
            m4.w = fmaxf(m4.w, lrelu(e1r.w + e2j.w));
        }
    }
#pragma unroll
    for (int o = 16; o; o >>= 1) {
        m4.x = fmaxf(m4.x, __shfl_xor_sync(0xffffffffu, m4.x, o));
        m4.y = fmaxf(m4.y, __shfl_xor_sync(0xffffffffu, m4.y, o));
        m4.z = fmaxf(m4.z, __shfl_xor_sync(0xffffffffu, m4.z, o));
        m4.w = fmaxf(m4.w, __shfl_xor_sync(0xffffffffu, m4.w, o));
    }

    // Stage-B role of this thread
    const int f4   = t & 15;            // float4 group of features
    const int hh   = (t >> 4) & 3;      // head
    const int sp   = t >> 6;            // jl-slice 0..3
    const int hoff = hh * 16 + f4;      // float4 index within a 256-wide h row

    float4 acc[RB];
#pragma unroll
    for (int r = 0; r < RB; r++) acc[r] = make_float4(0.f, 0.f, 0.f, 0.f);
    float4 z4 = make_float4(0.f, 0.f, 0.f, 0.f);

    for (int tile = 0; tile < NN / TJ; tile++) {
        __syncthreads();   // previous Stage B done before overwriting hsh/wsh

        // load h tile: 32 x 256 floats
        {
            const float4* src = (const float4*)(g_h + (size_t)tile * TJ * CTOT);
            float4* dst = (float4*)hsh;
#pragma unroll
            for (int q = 0; q < 8; q++) dst[t + q * 256] = src[t + q * 256];
        }
        // softmax weights for this tile: warp wrp -> row wrp, lane -> jl
        {
            const unsigned word = amask[wrp][tile];
            float4 wv = make_float4(0.f, 0.f, 0.f, 0.f);
            if (word & (1u << lane)) {
                const float4 e2j = *(const float4*)(g_e2 + (size_t)(tile * TJ + lane) * NHEADS);
                wv.x = __expf(lrelu(e1r.x + e2j.x) - m4.x);
                wv.y = __expf(lrelu(e1r.y + e2j.y) - m4.y);
                wv.z = __expf(lrelu(e1r.z + e2j.z) - m4.z);
                wv.w = __expf(lrelu(e1r.w + e2j.w) - m4.w);
                z4.x += wv.x; z4.y += wv.y; z4.z += wv.z; z4.w += wv.w;
            }
            wsh[wrp][lane] = wv;
        }
        __syncthreads();

        // Stage B: accumulate
        const float* wflat = (const float*)wsh;
#pragma unroll
        for (int q = 0; q < 8; q++) {
            const int jl = sp * 8 + q;
            const float4 hv = ((const float4*)(hsh + jl * CTOT))[hoff];
#pragma unroll
            for (int r = 0; r < RB; r++) {
                const float wv = wflat[(r * TJ + jl) * 4 + hh];
                acc[r].x += wv * hv.x;
                acc[r].y += wv * hv.y;
                acc[r].z += wv * hv.z;
                acc[r].w += wv * hv.w;
            }
        }
    }

    // Z reduce (per row, per head)
#pragma unroll
    for (int o = 16; o; o >>= 1) {
        z4.x += __shfl_xor_sync(0xffffffffu, z4.x, o);
        z4.y += __shfl_xor_sync(0xffffffffu, z4.y, o);
        z4.z += __shfl_xor_sync(0xffffffffu, z4.z, o);
        z4.w += __shfl_xor_sync(0xffffffffu, z4.w, o);
    }
    if (lane == 0) zsh[wrp] = z4;
    __syncthreads();

    // Epilogue: stash accumulators into hsh (reused), combine 4 slices,
    // divide by Z per head, mean over heads, write out.
    float4* ob = (float4*)hsh;
#pragma unroll
    for (int r = 0; r < RB; r++) ob[r * 256 + t] = acc[r];
    __syncthreads();

    if (t < 128) {
        const int r = t >> 4;
        const int g = t & 15;
        const float4 zz = zsh[r];
        const float invh[4] = { 0.25f / zz.x, 0.25f / zz.y, 0.25f / zz.z, 0.25f / zz.w };
        float4 o = make_float4(0.f, 0.f, 0.f, 0.f);
#pragma unroll
        for (int h2 = 0; h2 < 4; h2++) {
            float4 ssum = make_float4(0.f, 0.f, 0.f, 0.f);
#pragma unroll
            for (int s2 = 0; s2 < 4; s2++) {
                const float4 v = ob[r * 256 + s2 * 64 + h2 * 16 + g];
                ssum.x += v.x; ssum.y += v.y; ssum.z += v.z; ssum.w += v.w;
            }
            o.x += ssum.x * invh[h2];
            o.y += ssum.y * invh[h2];
            o.z += ssum.z * invh[h2];
            o.w += ssum.w * invh[h2];
        }
        *(float4*)(out + (size_t)(i0 + r) * FOUT_ + g * 4) = o;
    }
}

// ---------------------------------------------------------------------------
extern "C" void kernel_launch(void* const* d_in, const int* in_sizes, int n_in,
                              void* d_out, int out_size)
{
    const float* x   = (const float*)d_in[0];   // 4096 x 256
    const int*   adj = (const int*)  d_in[1];   // 4096 x 4096
    const float* W   = (const float*)d_in[2];   // 256 x 256
    const float* a   = (const float*)d_in[3];   // 128 x 1
    float* out = (float*)d_out;                 // 4096 x 64

    (void)in_sizes; (void)n_in; (void)out_size;

    k_proj<<<NN / 8, 256>>>(x, W, a);
    k_attn<<<NN / RB, 256>>>(adj, out);
}

// round 3
// speedup vs baseline: 1.1068x; 1.1068x over previous
#include <cuda_runtime.h>
#include <stdint.h>

#define NN     4096
#define FIN    256
#define NHEADS 4
#define FOUT_  64
#define CTOT   256   // NHEADS*FOUT_
#define RB     8     // rows of i per attention block
#define TJ     32    // j-tile staged in shared

// Scratch (no allocations allowed): h = x@W, e1 = h.a1 (per head), e2 = h.a2
__device__ float g_h [NN * CTOT];
__device__ float g_e1[NN * NHEADS];
__device__ float g_e2[NN * NHEADS];

__device__ __forceinline__ float lrelu(float s) { return fmaxf(s, 0.2f * s); }

// packed fp32x2 FMA: d = a*b + d  (Blackwell-only, PTX-only)
__device__ __forceinline__ void ffma2(unsigned long long& d,
                                      unsigned long long a,
                                      unsigned long long b)
{
    asm("fma.rn.f32x2 %0, %1, %2, %0;" : "+l"(d) : "l"(a), "l"(b));
}

union UF { unsigned long long u; float2 f; };
__device__ __forceinline__ float4 mk4(unsigned long long a, unsigned long long b)
{
    UF x; x.u = a; UF y; y.u = b;
    return make_float4(x.f.x, x.f.y, y.f.x, y.f.y);
}

// ---------------------------------------------------------------------------
// Kernel 1: h = x @ W  (4096x256 @ 256x256), plus e1[n][h], e2[n][h].
// ---------------------------------------------------------------------------
__global__ __launch_bounds__(256) void k_proj(const float* __restrict__ x,
                                              const float* __restrict__ W,
                                              const float* __restrict__ a)
{
    const int t  = threadIdx.x;         // output channel c = t
    const int n0 = blockIdx.x * 8;

    __shared__ float sx[8][FIN];
    {
        const float4* xs = (const float4*)(x + (size_t)n0 * FIN);
        float4* ss = (float4*)&sx[0][0];
        ss[t]       = xs[t];
        ss[t + 256] = xs[t + 256];
    }
    __syncthreads();

    float acc[8];
#pragma unroll
    for (int r = 0; r < 8; r++) acc[r] = 0.f;

#pragma unroll 4
    for (int k = 0; k < FIN; k++) {
        const float wv = W[k * CTOT + t];
#pragma unroll
        for (int r = 0; r < 8; r++) acc[r] += sx[r][k] * wv;
    }

    const int f = t & 63;
    const float a1 = a[f];
    const float a2 = a[64 + f];

    __shared__ float red1[8], red2[8];
#pragma unroll
    for (int r = 0; r < 8; r++) {
        g_h[(size_t)(n0 + r) * CTOT + t] = acc[r];
        float p1 = acc[r] * a1;
        float p2 = acc[r] * a2;
#pragma unroll
        for (int o = 16; o; o >>= 1) {
            p1 += __shfl_xor_sync(0xffffffffu, p1, o);
            p2 += __shfl_xor_sync(0xffffffffu, p2, o);
        }
        const int w = t >> 5;
        if ((t & 31) == 0) { red1[w] = p1; red2[w] = p2; }
        __syncthreads();
        if (t < 4) {
            g_e1[(size_t)(n0 + r) * NHEADS + t] = red1[2 * t] + red1[2 * t + 1];
            g_e2[(size_t)(n0 + r) * NHEADS + t] = red2[2 * t] + red2[2 * t + 1];
        }
        __syncthreads();
    }
}

// ---------------------------------------------------------------------------
// Kernel 2: masked softmax + aggregation, 8 rows i per block.
//   Warp wrp: builds adjacency bitmask + softmax weights for row i0+wrp.
//   Stage B: warp w processes jl = w*4..w*4+3; each thread owns 8 channels
//   (channels lane*4..+3 and 128+lane*4..+3) for all 8 rows, accumulated
//   with packed fma.rn.f32x2. h loads are dense (conflict-free), weight
//   loads are 4-address broadcasts of pre-duplicated {w,w} pairs.
// ---------------------------------------------------------------------------
__global__ __launch_bounds__(256, 2) void k_attn(const int* __restrict__ adj,
                                                 float* __restrict__ out)
{
    const int t    = threadIdx.x;
    const int lane = t & 31;
    const int wrp  = t >> 5;            // 0..7
    const int i0   = blockIdx.x * RB;

    __shared__ unsigned amask[RB][NN / 32];   // 4 KB
    __shared__ float    hsh[TJ * CTOT];       // 32 KB (reused for epilogue)
    __shared__ float2   wsh2[RB * TJ * 4];    // 8 KB, {w,w} per (r,jl,head)
    __shared__ float4   zsh[RB];

    // 1. adjacency -> bitmask (adj read exactly once per row)
    {
        const int* arow = adj + (size_t)(i0 + wrp) * NN;
#pragma unroll 4
        for (int b = 0; b < NN / 32; b++) {
            unsigned m = __ballot_sync(0xffffffffu, arow[b * 32 + lane] != 0);
            if (lane == 0) amask[wrp][b] = m;
        }
    }
    const float4 e1r = *(const float4*)(g_e1 + (size_t)(i0 + wrp) * NHEADS);
    __syncthreads();

    // 2. exact row max per head (warp wrp -> row wrp)
    float4 m4 = make_float4(-1e30f, -1e30f, -1e30f, -1e30f);
    for (int it = 0; it < NN / 32; it++) {
        const unsigned word = amask[wrp][it];
        if (word & (1u << lane)) {
            const float4 e2j = *(const float4*)(g_e2 + (size_t)(it * 32 + lane) * NHEADS);
            m4.x = fmaxf(m4.x, lrelu(e1r.x + e2j.x));
            m4.y = fmaxf(m4.y, lrelu(e1r.y + e2j.y));
            m4.z = fmaxf(m4.z, lrelu(e1r.z + e2j.z));
            m4.w = fmaxf(m4.w, lrelu(e1r.w + e2j.w));
        }
    }
#pragma unroll
    for (int o = 16; o; o >>= 1) {
        m4.x = fmaxf(m4.x, __shfl_xor_sync(0xffffffffu, m4.x, o));
        m4.y = fmaxf(m4.y, __shfl_xor_sync(0xffffffffu, m4.y, o));
        m4.z = fmaxf(m4.z, __shfl_xor_sync(0xffffffffu, m4.z, o));
        m4.w = fmaxf(m4.w, __shfl_xor_sync(0xffffffffu, m4.w, o));
    }

    const int h1 = lane >> 4;            // head of channel-set 1 (set 2 = h1+2)

    // acc[r][0..1] -> channels lane*4..+3 ; acc[r][2..3] -> 128+lane*4..+3
    unsigned long long acc[RB][4];
#pragma unroll
    for (int r = 0; r < RB; r++)
#pragma unroll
        for (int q = 0; q < 4; q++) acc[r][q] = 0ull;

    float4 z4 = make_float4(0.f, 0.f, 0.f, 0.f);
    const unsigned long long* wp = (const unsigned long long*)wsh2;

    for (int tile = 0; tile < NN / TJ; tile++) {
        __syncthreads();   // previous Stage B done before overwriting hsh/wsh2

        // load h tile: 32 x 256 floats (32 KB)
        {
            const float4* src = (const float4*)(g_h + (size_t)tile * TJ * CTOT);
            float4* dst = (float4*)hsh;
#pragma unroll
            for (int q = 0; q < 8; q++) dst[t + q * 256] = src[t + q * 256];
        }
        // softmax weights for this tile: warp wrp -> row wrp, lane -> jl
        {
            const unsigned word = amask[wrp][tile];
            float4 wv = make_float4(0.f, 0.f, 0.f, 0.f);
            if (word & (1u << lane)) {
                const float4 e2j = *(const float4*)(g_e2 + (size_t)(tile * TJ + lane) * NHEADS);
                wv.x = __expf(lrelu(e1r.x + e2j.x) - m4.x);
                wv.y = __expf(lrelu(e1r.y + e2j.y) - m4.y);
                wv.z = __expf(lrelu(e1r.z + e2j.z) - m4.z);
                wv.w = __expf(lrelu(e1r.w + e2j.w) - m4.w);
                z4.x += wv.x; z4.y += wv.y; z4.z += wv.z; z4.w += wv.w;
            }
            const int b = (wrp * TJ + lane) * 4;
            wsh2[b + 0] = make_float2(wv.x, wv.x);
            wsh2[b + 1] = make_float2(wv.y, wv.y);
            wsh2[b + 2] = make_float2(wv.z, wv.z);
            wsh2[b + 3] = make_float2(wv.w, wv.w);
        }
        __syncthreads();

        // Stage B: warp wrp handles jl = wrp*4 .. wrp*4+3
#pragma unroll
        for (int jj = 0; jj < 4; jj++) {
            const int jl = wrp * 4 + jj;
            const float* hrow = hsh + jl * CTOT;
            const ulonglong2 ha = *(const ulonglong2*)(hrow + lane * 4);
            const ulonglong2 hb = *(const ulonglong2*)(hrow + 128 + lane * 4);
            const int wbase = jl * 4 + h1;
#pragma unroll
            for (int r = 0; r < RB; r++) {
                const unsigned long long wA = wp[r * (TJ * 4) + wbase];
                const unsigned long long wB = wp[r * (TJ * 4) + wbase + 2];
                ffma2(acc[r][0], wA, ha.x);
                ffma2(acc[r][1], wA, ha.y);
                ffma2(acc[r][2], wB, hb.x);
                ffma2(acc[r][3], wB, hb.y);
            }
        }
    }

    // Z reduce (per row, per head); zsh written before the epilogue syncs
#pragma unroll
    for (int o = 16; o; o >>= 1) {
        z4.x += __shfl_xor_sync(0xffffffffu, z4.x, o);
        z4.y += __shfl_xor_sync(0xffffffffu, z4.y, o);
        z4.z += __shfl_xor_sync(0xffffffffu, z4.z, o);
        z4.w += __shfl_xor_sync(0xffffffffu, z4.w, o);
    }
    if (lane == 0) zsh[wrp] = z4;

    // Epilogue: one row at a time. 8 warp-partials (256 floats each) -> hsh,
    // then 64 threads reduce across warps + heads, divide by Z, mean, store.
#pragma unroll
    for (int r = 0; r < RB; r++) {
        __syncthreads();
        float4* ob = (float4*)hsh;
        ob[wrp * 64 + lane]      = mk4(acc[r][0], acc[r][1]);
        ob[wrp * 64 + 32 + lane] = mk4(acc[r][2], acc[r][3]);
        __syncthreads();
        if (t < 64) {
            const float4 zz = zsh[r];
            const float inv[4] = { 0.25f / zz.x, 0.25f / zz.y,
                                   0.25f / zz.z, 0.25f / zz.w };
            float o = 0.f;
#pragma unroll
            for (int h2 = 0; h2 < 4; h2++) {
                float s = 0.f;
#pragma unroll
                for (int w2 = 0; w2 < 8; w2++) s += hsh[w2 * 256 + h2 * 64 + t];
                o += s * inv[h2];
            }
            out[(size_t)(i0 + r) * FOUT_ + t] = o;
        }
    }
}

// ---------------------------------------------------------------------------
extern "C" void kernel_launch(void* const* d_in, const int* in_sizes, int n_in,
                              void* d_out, int out_size)
{
    const float* x   = (const float*)d_in[0];   // 4096 x 256
    const int*   adj = (const int*)  d_in[1];   // 4096 x 4096
    const float* W   = (const float*)d_in[2];   // 256 x 256
    const float* a   = (const float*)d_in[3];   // 128 x 1
    float* out = (float*)d_out;                 // 4096 x 64

    (void)in_sizes; (void)n_in; (void)out_size;

    k_proj<<<NN / 8, 256>>>(x, W, a);
    k_attn<<<NN / RB, 256>>>(adj, out);
}